// round 1
// baseline (speedup 1.0000x reference)
#include <cuda_runtime.h>
#include <math.h>

// Problem constants
#define BB 8
#define PP 512
#define LL 64
#define HH 128
#define RBN 32
#define NPT 20
#define NLT 16

// Tiles: 128 pairs per tile (2 protein atoms x 64 ligand atoms)
#define TILES_PER_CPLX 256          // P*L/128
#define NTILES (BB * TILES_PER_CPLX)

// SMEM layout (in floats)
#define OFF_W1R 0                   // [32][128]   = 4096
#define OFF_W2  4096                // [128][128]  = 16384
#define OFF_W3  20480               // [128][128]  = 16384
#define OFF_HT  36864               // [128][132]  = 16896 (transposed h, pitch 132)
#define OFF_RBT 53760               // [32][128]   = 4096  (transposed rb)
#define OFF_MSK 57856               // [128]
#define SMEM_FLOATS 57984           // 231,936 bytes
#define HT_PITCH 132

// Scratch (recomputed every launch by prep_kernel — deterministic)
__device__ float gPtab[NPT * HH];   // prot_emb@W1[0:128] + b1
__device__ float gLtab[NLT * HH];   // lig_emb@W1[128:256]
__device__ float gAccum[BB * HH];   // masked sum of h3 per complex
__device__ int   gCnt[BB];          // masked pair count per complex

// ---------------------------------------------------------------------------
// Kernel 0: build type tables, zero accumulators
// ---------------------------------------------------------------------------
__global__ void prep_kernel(const float* __restrict__ prot_emb,
                            const float* __restrict__ lig_emb,
                            const float* __restrict__ W1,
                            const float* __restrict__ b1) {
    int bid = blockIdx.x;
    int c = threadIdx.x;  // 0..127
    if (bid < NPT) {
        float s = b1[c];
        const float* e = prot_emb + bid * HH;
        #pragma unroll 4
        for (int k = 0; k < HH; k++) s += e[k] * W1[k * HH + c];
        gPtab[bid * HH + c] = s;
    } else if (bid < NPT + NLT) {
        int t = bid - NPT;
        float s = 0.f;
        const float* e = lig_emb + t * HH;
        #pragma unroll 4
        for (int k = 0; k < HH; k++) s += e[k] * W1[(HH + k) * HH + c];
        gLtab[t * HH + c] = s;
    } else {
        for (int i = c; i < BB * HH; i += HH) gAccum[i] = 0.f;
        if (c < BB) gCnt[c] = 0;
    }
}

// ---------------------------------------------------------------------------
// Register-tile GEMM fragment: acc[8][8] += A^T-frag * B-frag
// A stored transposed: A[k*APITCH + m]; B row-major: B[k*128 + c]
// ---------------------------------------------------------------------------
template<int K, int APITCH>
__device__ __forceinline__ void gemm_frag(const float* __restrict__ A,
                                          const float* __restrict__ Bw,
                                          int r0, int c0, float acc[8][8]) {
    #pragma unroll 2
    for (int k = 0; k < K; k++) {
        const float* ap = A + k * APITCH + r0;
        float4 A0 = *(const float4*)(ap);
        float4 A1 = *(const float4*)(ap + 4);
        const float* bp = Bw + k * HH + c0;
        float4 B0 = *(const float4*)(bp);
        float4 B1 = *(const float4*)(bp + 4);
        float av[8] = {A0.x, A0.y, A0.z, A0.w, A1.x, A1.y, A1.z, A1.w};
        float bv[8] = {B0.x, B0.y, B0.z, B0.w, B1.x, B1.y, B1.z, B1.w};
        #pragma unroll
        for (int i = 0; i < 8; i++)
            #pragma unroll
            for (int j = 0; j < 8; j++)
                acc[i][j] = fmaf(av[i], bv[j], acc[i][j]);
    }
}

__device__ __forceinline__ void write_ht(float* __restrict__ sHT,
                                         int r0, int c0, const float acc[8][8]) {
    #pragma unroll
    for (int j = 0; j < 8; j++) {
        float4 v0 = make_float4(acc[0][j], acc[1][j], acc[2][j], acc[3][j]);
        float4 v1 = make_float4(acc[4][j], acc[5][j], acc[6][j], acc[7][j]);
        float* dst = sHT + (c0 + j) * HT_PITCH + r0;
        *(float4*)(dst)     = v0;
        *(float4*)(dst + 4) = v1;
    }
}

// ---------------------------------------------------------------------------
// Kernel 1: fused pair MLP + masked accumulation (persistent CTAs)
// ---------------------------------------------------------------------------
__global__ __launch_bounds__(256, 1)
void main_kernel(const float* __restrict__ ppos, const float* __restrict__ lpos,
                 const float* __restrict__ W1, const float* __restrict__ W2,
                 const float* __restrict__ b2, const float* __restrict__ W3,
                 const float* __restrict__ b3,
                 const int* __restrict__ ptype, const int* __restrict__ ltype) {
    extern __shared__ float sm[];
    float* sW1r = sm + OFF_W1R;
    float* sW2  = sm + OFF_W2;
    float* sW3  = sm + OFF_W3;
    float* sHT  = sm + OFF_HT;
    float* sRBT = sm + OFF_RBT;
    float* sMsk = sm + OFF_MSK;

    const int tid = threadIdx.x;

    // Load weights into SMEM once per CTA
    {
        const float4* s1 = (const float4*)(W1 + 256 * HH);  // rb rows of W1
        float4* d1 = (float4*)sW1r;
        for (int i = tid; i < (RBN * HH) / 4; i += 256) d1[i] = s1[i];
        const float4* s2 = (const float4*)W2; float4* d2 = (float4*)sW2;
        for (int i = tid; i < (HH * HH) / 4; i += 256) d2[i] = s2[i];
        const float4* s3 = (const float4*)W3; float4* d3 = (float4*)sW3;
        for (int i = tid; i < (HH * HH) / 4; i += 256) d3[i] = s3[i];
    }

    const int rg = tid & 15;        // row group
    const int cg = tid >> 4;        // col group
    const int r0 = rg * 8;
    const int c0 = cg * 8;

    float rb2[8], rb3[8];
    #pragma unroll
    for (int j = 0; j < 8; j++) { rb2[j] = b2[c0 + j]; rb3[j] = b3[c0 + j]; }
    __syncthreads();

    const float invw  = 1.0f / (0.125f + 1e-8f);   // matches reference fp32 expr
    const float cstep = 8.0f / 31.0f;              // linspace(0,8,32) step

    const int m_   = tid >> 1;      // pair handled in phase 1
    const int half = tid & 1;       // which 16 radial bins

    for (int tile = blockIdx.x; tile < NTILES; tile += gridDim.x) {
        const int b  = tile >> 8;       // tile / 256
        const int ti = tile & 255;

        // ---- Phase 1: distances, radial basis (transposed), mask ----
        int pred;
        {
            const int pl = ti * 2 + (m_ >> 6);
            const int ll = m_ & 63;
            const float* pp = ppos + (size_t)(b * PP + pl) * 3;
            const float* lp = lpos + (size_t)(b * LL + ll) * 3;
            const float dx = pp[0] - lp[0];
            const float dy = pp[1] - lp[1];
            const float dz = pp[2] - lp[2];
            const float dist = sqrtf(dx * dx + dy * dy + dz * dz);
            const int maskp = dist < 8.0f;
            if (half == 0) sMsk[m_] = maskp ? 1.0f : 0.0f;
            const int bin0 = half * 16;
            #pragma unroll
            for (int jb = 0; jb < 16; jb++) {
                const int bin = bin0 + jb;
                const float t = (dist - (float)bin * cstep) * invw;
                sRBT[bin * HH + m_] = __expf(-0.5f * t * t);
            }
            pred = (half == 0) && maskp;
        }

        const int tileCnt = __syncthreads_count(pred);
        if (tileCnt == 0) continue;   // whole tile outside cutoff

        float acc[8][8];

        // ---- Layer 1: rb @ W1r + Ptab[pt] + Ltab[lt], relu ----
        #pragma unroll
        for (int i = 0; i < 8; i++)
            #pragma unroll
            for (int j = 0; j < 8; j++) acc[i][j] = 0.f;
        gemm_frag<RBN, HH>(sRBT, sW1r, r0, c0, acc);
        {
            const int pl = ti * 2 + (r0 >> 6);            // 8 rows share one p-atom
            const int pt = ptype[b * PP + pl];
            const float* pB = gPtab + pt * HH + c0;
            float pv[8];
            #pragma unroll
            for (int j = 0; j < 8; j++) pv[j] = pB[j];
            #pragma unroll
            for (int i = 0; i < 8; i++) {
                const int ll = (r0 & 63) + i;
                const int lt = ltype[b * LL + ll];
                const float* lB = gLtab + lt * HH + c0;
                #pragma unroll
                for (int j = 0; j < 8; j++)
                    acc[i][j] = fmaxf(acc[i][j] + pv[j] + lB[j], 0.f);
            }
        }
        write_ht(sHT, r0, c0, acc);
        __syncthreads();

        // ---- Layer 2 ----
        #pragma unroll
        for (int i = 0; i < 8; i++)
            #pragma unroll
            for (int j = 0; j < 8; j++) acc[i][j] = 0.f;
        gemm_frag<HH, HT_PITCH>(sHT, sW2, r0, c0, acc);
        #pragma unroll
        for (int i = 0; i < 8; i++)
            #pragma unroll
            for (int j = 0; j < 8; j++)
                acc[i][j] = fmaxf(acc[i][j] + rb2[j], 0.f);
        __syncthreads();              // everyone done reading h1
        write_ht(sHT, r0, c0, acc);
        __syncthreads();

        // ---- Layer 3 + masked accumulation ----
        #pragma unroll
        for (int i = 0; i < 8; i++)
            #pragma unroll
            for (int j = 0; j < 8; j++) acc[i][j] = 0.f;
        gemm_frag<HH, HT_PITCH>(sHT, sW3, r0, c0, acc);

        float csum[8];
        #pragma unroll
        for (int j = 0; j < 8; j++) csum[j] = 0.f;
        #pragma unroll
        for (int i = 0; i < 8; i++) {
            const float mk = sMsk[r0 + i];
            #pragma unroll
            for (int j = 0; j < 8; j++) {
                const float v = fmaxf(acc[i][j] + rb3[j], 0.f);
                csum[j] += mk * v;
            }
        }
        // reduce over the 16 row-groups (lanes 0-15 / 16-31 are separate cgs)
        #pragma unroll
        for (int j = 0; j < 8; j++) {
            #pragma unroll
            for (int off = 1; off < 16; off <<= 1)
                csum[j] += __shfl_xor_sync(0xffffffffu, csum[j], off);
        }
        if (rg == 0) {
            #pragma unroll
            for (int j = 0; j < 8; j++)
                atomicAdd(&gAccum[b * HH + c0 + j], csum[j]);
        }
        if (tid == 0) atomicAdd(&gCnt[b], tileCnt);
        __syncthreads();              // protect sMsk/sRBT for next tile
    }
}

// ---------------------------------------------------------------------------
// Kernel 2: readout MLP per complex
// ---------------------------------------------------------------------------
__global__ void finalize_kernel(const float* __restrict__ Wr1,
                                const float* __restrict__ br1,
                                const float* __restrict__ Wr2,
                                const float* __restrict__ br2,
                                float* __restrict__ out) {
    const int b = blockIdx.x;
    const int c = threadIdx.x;   // 0..127
    __shared__ float repr[HH];
    __shared__ float red[HH];
    const int cnt = gCnt[b];
    const float denom = fmaxf((float)cnt, 1.0f);
    repr[c] = gAccum[b * HH + c] / denom;
    __syncthreads();
    float t = br1[c];
    #pragma unroll 4
    for (int k = 0; k < HH; k++) t += repr[k] * Wr1[k * HH + c];
    t = fmaxf(t, 0.f);
    red[c] = t * Wr2[c];
    __syncthreads();
    for (int s = 64; s > 0; s >>= 1) {
        if (c < s) red[c] += red[c + s];
        __syncthreads();
    }
    if (c == 0) out[b] = (cnt > 0) ? (red[0] + br2[0]) : 0.0f;
}

// ---------------------------------------------------------------------------
extern "C" void kernel_launch(void* const* d_in, const int* in_sizes, int n_in,
                              void* d_out, int out_size) {
    const float* ppos = (const float*)d_in[0];
    const float* lpos = (const float*)d_in[1];
    const float* pemb = (const float*)d_in[2];
    const float* lemb = (const float*)d_in[3];
    const float* W1   = (const float*)d_in[4];
    const float* b1   = (const float*)d_in[5];
    const float* W2   = (const float*)d_in[6];
    const float* b2   = (const float*)d_in[7];
    const float* W3   = (const float*)d_in[8];
    const float* b3   = (const float*)d_in[9];
    const float* Wr1  = (const float*)d_in[10];
    const float* br1  = (const float*)d_in[11];
    const float* Wr2  = (const float*)d_in[12];
    const float* br2  = (const float*)d_in[13];
    const int*   pt   = (const int*)d_in[14];
    const int*   lt   = (const int*)d_in[15];
    float* out = (float*)d_out;

    const int smemBytes = SMEM_FLOATS * sizeof(float);
    cudaFuncSetAttribute(main_kernel,
                         cudaFuncAttributeMaxDynamicSharedMemorySize, smemBytes);

    prep_kernel<<<NPT + NLT + 1, HH>>>(pemb, lemb, W1, b1);
    main_kernel<<<148, 256, smemBytes>>>(ppos, lpos, W1, W2, b2, W3, b3, pt, lt);
    finalize_kernel<<<BB, HH>>>(Wr1, br1, Wr2, br2, out);
}

// round 6
// speedup vs baseline: 2.6927x; 2.6927x over previous
#include <cuda_runtime.h>
#include <cstdint>
#include <math.h>

// Problem constants
#define BB 8
#define PP 512
#define LL 64
#define HH 128
#define NPT 20
#define NLT 16
#define NTILES (BB * 256)      // 2048 tiles of 128 pairs (2 p-atoms x 64 l-atoms)
#define GRIDX 148

// SMEM layout (float indices). Weights stored n-major [n][k] (B-fragment friendly).
#define W1R_PITCH 36
#define W_PITCH   132
#define H_PITCH   132
#define OFF_W1R 0                        // [128][36]   = 4608
#define OFF_W2  4608                     // [128][132]  = 16896
#define OFF_W3  21504                    // [128][132]  = 16896
#define OFF_H   38400                    // [128][132]  = 16896
#define OFF_MSK 55296                    // [128]
#define OFF_B2  55424                    // [128]
#define OFF_B3  55552                    // [128]
#define SMEM_FLOATS 55680                // 222,720 bytes
#define SMEM_BYTES (SMEM_FLOATS * 4)

// Global scratch (deterministic: rebuilt every launch)
__device__ float gPtab[NPT * HH];   // prot_emb@W1[0:128] + b1
__device__ float gLtab[NLT * HH];   // lig_emb@W1[128:256]
__device__ float gAccum[BB * HH];
__device__ int   gCnt[BB];

// ---------------------------------------------------------------------------
// tf32 destination must be a .b32 register in PTX -> "=r" constraint.
__device__ __forceinline__ float to_tf32(float x) {
    uint32_t y;
    asm("cvt.rna.tf32.f32 %0, %1;" : "=r"(y) : "f"(x));
    return __uint_as_float(y);
}

__device__ __forceinline__ void mma_tf32(float c[4], const uint32_t a[4],
                                         uint32_t b0, uint32_t b1) {
    asm volatile(
        "mma.sync.aligned.m16n8k8.row.col.f32.tf32.tf32.f32 "
        "{%0,%1,%2,%3}, {%4,%5,%6,%7}, {%8,%9}, {%0,%1,%2,%3};"
        : "+f"(c[0]), "+f"(c[1]), "+f"(c[2]), "+f"(c[3])
        : "r"(a[0]), "r"(a[1]), "r"(a[2]), "r"(a[3]), "r"(b0), "r"(b1));
}

// Warp-level GEMM: acc[mt][nt][] += A(h)[mrow0..+32, 0..K) @ W[n][k]^T
template<int KSTEPS, int WPITCH>
__device__ __forceinline__ void layer_mma(const float* __restrict__ hA,
                                          const float* __restrict__ Wb,
                                          int mrow0, int ncol0, int lane,
                                          float acc[2][8][4]) {
    const int gr = lane >> 2, tig = lane & 3;
    #pragma unroll
    for (int ks = 0; ks < KSTEPS; ks++) {
        uint32_t a[2][4];
        #pragma unroll
        for (int mt = 0; mt < 2; mt++) {
            const float* base = hA + (mrow0 + mt * 16 + gr) * H_PITCH + ks * 8 + tig;
            a[mt][0] = __float_as_uint(base[0]);
            a[mt][1] = __float_as_uint(base[8 * H_PITCH]);
            a[mt][2] = __float_as_uint(base[4]);
            a[mt][3] = __float_as_uint(base[8 * H_PITCH + 4]);
        }
        #pragma unroll
        for (int nt = 0; nt < 8; nt++) {
            const float* bp = Wb + (ncol0 + nt * 8 + gr) * WPITCH + ks * 8 + tig;
            uint32_t b0 = __float_as_uint(bp[0]);
            uint32_t b1 = __float_as_uint(bp[4]);
            mma_tf32(acc[0][nt], a[0], b0, b1);
            mma_tf32(acc[1][nt], a[1], b0, b1);
        }
    }
}

// ---------------------------------------------------------------------------
__global__ void zero_kernel() {
    int i = threadIdx.x;
    for (int j = i; j < BB * HH; j += 256) gAccum[j] = 0.f;
    if (i < BB) gCnt[i] = 0;
}

// ---------------------------------------------------------------------------
// Main kernel: fused pair MLP via mma.sync tf32, persistent CTAs
// ---------------------------------------------------------------------------
__global__ __launch_bounds__(256, 1)
void main_kernel(const float* __restrict__ ppos, const float* __restrict__ lpos,
                 const float* __restrict__ pemb, const float* __restrict__ lemb,
                 const float* __restrict__ W1, const float* __restrict__ b1,
                 const float* __restrict__ W2, const float* __restrict__ b2,
                 const float* __restrict__ W3, const float* __restrict__ b3,
                 const int* __restrict__ ptype, const int* __restrict__ ltype) {
    extern __shared__ float sm[];
    float* sW1r = sm + OFF_W1R;
    float* sW2  = sm + OFF_W2;
    float* sW3  = sm + OFF_W3;
    float* sH   = sm + OFF_H;
    float* sMsk = sm + OFF_MSK;

    const int tid = threadIdx.x;
    const int w = tid >> 5;
    const int lane = tid & 31;
    const int gr = lane >> 2, tig = lane & 3;

    // ---- Prologue: stage weights (tf32-rounded, n-major) ----
    for (int idx = tid; idx < 32 * 128; idx += 256) {     // W1 radial rows
        int k = idx >> 7, n = idx & 127;
        sW1r[n * W1R_PITCH + k] = to_tf32(W1[(256 + k) * 128 + n]);
    }
    for (int idx = tid; idx < 128 * 128; idx += 256) {
        int k = idx >> 7, n = idx & 127;
        sW2[n * W_PITCH + k] = to_tf32(W2[k * 128 + n]);
        sW3[n * W_PITCH + k] = to_tf32(W3[k * 128 + n]);
    }
    if (tid < 128) { sm[OFF_B2 + tid] = b2[tid]; sm[OFF_B3 + tid] = b3[tid]; }

    // ---- Prologue: type tables (each CTA redundantly writes identical data) ----
    {
        const int c = tid & 127;
        if (tid < 128) {
            float tab[NPT];
            #pragma unroll
            for (int t = 0; t < NPT; t++) tab[t] = 0.f;
            for (int k = 0; k < 128; k++) {
                float wv = W1[k * 128 + c];
                #pragma unroll
                for (int t = 0; t < NPT; t++) tab[t] += wv * pemb[t * 128 + k];
            }
            float bb = b1[c];
            #pragma unroll
            for (int t = 0; t < NPT; t++) gPtab[t * 128 + c] = tab[t] + bb;
        } else {
            float tab[NLT];
            #pragma unroll
            for (int t = 0; t < NLT; t++) tab[t] = 0.f;
            for (int k = 0; k < 128; k++) {
                float wv = W1[(128 + k) * 128 + c];
                #pragma unroll
                for (int t = 0; t < NLT; t++) tab[t] += wv * lemb[t * 128 + k];
            }
            #pragma unroll
            for (int t = 0; t < NLT; t++) gLtab[t * 128 + c] = tab[t];
        }
    }
    __syncthreads();   // orders SMEM staging + own global table writes

    const int mrow0 = (w & 3) * 32;
    const int ncol0 = (w >> 2) * 64;

    float accum[16];
    #pragma unroll
    for (int j = 0; j < 16; j++) accum[j] = 0.f;
    int cur_b = -1, cnt_local = 0;

    const float invw  = 1.0f / (0.125f + 1e-8f);
    const float cstep = 8.0f / 31.0f;
    const int m_   = tid >> 1;      // pair handled in phase 1
    const int half = tid & 1;
    const int t_begin = (blockIdx.x * NTILES) / GRIDX;
    const int t_end   = ((blockIdx.x + 1) * NTILES) / GRIDX;

    auto flush = [&]() {
        #pragma unroll
        for (int j = 0; j < 16; j++) {
            #pragma unroll
            for (int off = 4; off < 32; off <<= 1)
                accum[j] += __shfl_xor_sync(0xffffffffu, accum[j], off);
        }
        if (lane < 4) {
            #pragma unroll
            for (int nt = 0; nt < 8; nt++) {
                atomicAdd(&gAccum[cur_b * HH + ncol0 + nt * 8 + lane * 2],     accum[nt * 2]);
                atomicAdd(&gAccum[cur_b * HH + ncol0 + nt * 8 + lane * 2 + 1], accum[nt * 2 + 1]);
            }
        }
        if (tid == 0) atomicAdd(&gCnt[cur_b], cnt_local);
        #pragma unroll
        for (int j = 0; j < 16; j++) accum[j] = 0.f;
    };

    for (int t = t_begin; t < t_end; t++) {
        const int b = t >> 8, ti = t & 255;
        if (b != cur_b) {
            if (cur_b >= 0) flush();
            cur_b = b; cnt_local = 0;
        }

        __syncthreads();   // protect sH/sMsk from previous tile's readers

        // ---- Phase 1: distances + tf32 radial basis into sH cols 0..31 ----
        {
            const int pl = ti * 2 + (m_ >> 6);
            const int ll = m_ & 63;
            const float* pp = ppos + (size_t)(b * PP + pl) * 3;
            const float* lp = lpos + (size_t)(b * LL + ll) * 3;
            const float dx = pp[0] - lp[0], dy = pp[1] - lp[1], dz = pp[2] - lp[2];
            const float dist = sqrtf(dx * dx + dy * dy + dz * dz);
            if (half == 0) sMsk[m_] = (dist < 8.0f) ? 1.0f : 0.0f;
            #pragma unroll
            for (int j = 0; j < 16; j++) {
                const int bin = half * 16 + j;
                const float tt = (dist - (float)bin * cstep) * invw;
                sH[m_ * H_PITCH + bin] = to_tf32(__expf(-0.5f * tt * tt));
            }
            const int cnt = __syncthreads_count(half == 0 && dist < 8.0f);
            if (cnt == 0) continue;
            if (tid == 0) cnt_local += cnt;   // only tid 0 tracks; flush uses tid 0
        }

        float acc[2][8][4];

        // ---- Layer 1: rb @ W1r ----
        #pragma unroll
        for (int mt = 0; mt < 2; mt++)
            #pragma unroll
            for (int nt = 0; nt < 8; nt++)
                #pragma unroll
                for (int j = 0; j < 4; j++) acc[mt][nt][j] = 0.f;
        layer_mma<4, W1R_PITCH>(sH, sW1r, mrow0, ncol0, lane, acc);

        // ---- Epilogue 1: + Ptab[pt] + Ltab[lt], relu -> sH (tf32) ----
        __syncthreads();   // all warps done reading rb
        {
            const int pl = ti * 2 + ((w & 3) >> 1);
            const int pt = ptype[b * PP + pl];
            const float* PT = gPtab + pt * 128;
            #pragma unroll
            for (int mt = 0; mt < 2; mt++) {
                const int r1 = mrow0 + mt * 16 + gr;
                const int r2 = r1 + 8;
                const float* L1 = gLtab + ltype[b * LL + (r1 & 63)] * 128;
                const float* L2 = gLtab + ltype[b * LL + (r2 & 63)] * 128;
                #pragma unroll
                for (int nt = 0; nt < 8; nt++) {
                    const int c = ncol0 + nt * 8 + tig * 2;
                    const float p0 = PT[c], p1 = PT[c + 1];
                    float2 v1, v2;
                    v1.x = to_tf32(fmaxf(acc[mt][nt][0] + p0 + L1[c],     0.f));
                    v1.y = to_tf32(fmaxf(acc[mt][nt][1] + p1 + L1[c + 1], 0.f));
                    v2.x = to_tf32(fmaxf(acc[mt][nt][2] + p0 + L2[c],     0.f));
                    v2.y = to_tf32(fmaxf(acc[mt][nt][3] + p1 + L2[c + 1], 0.f));
                    *(float2*)(sH + r1 * H_PITCH + c) = v1;
                    *(float2*)(sH + r2 * H_PITCH + c) = v2;
                }
            }
        }
        __syncthreads();

        // ---- Layer 2 ----
        #pragma unroll
        for (int mt = 0; mt < 2; mt++)
            #pragma unroll
            for (int nt = 0; nt < 8; nt++)
                #pragma unroll
                for (int j = 0; j < 4; j++) acc[mt][nt][j] = 0.f;
        layer_mma<16, W_PITCH>(sH, sW2, mrow0, ncol0, lane, acc);
        __syncthreads();
        {
            #pragma unroll
            for (int mt = 0; mt < 2; mt++) {
                const int r1 = mrow0 + mt * 16 + gr;
                const int r2 = r1 + 8;
                #pragma unroll
                for (int nt = 0; nt < 8; nt++) {
                    const int c = ncol0 + nt * 8 + tig * 2;
                    const float b0 = sm[OFF_B2 + c], b1v = sm[OFF_B2 + c + 1];
                    float2 v1, v2;
                    v1.x = to_tf32(fmaxf(acc[mt][nt][0] + b0,  0.f));
                    v1.y = to_tf32(fmaxf(acc[mt][nt][1] + b1v, 0.f));
                    v2.x = to_tf32(fmaxf(acc[mt][nt][2] + b0,  0.f));
                    v2.y = to_tf32(fmaxf(acc[mt][nt][3] + b1v, 0.f));
                    *(float2*)(sH + r1 * H_PITCH + c) = v1;
                    *(float2*)(sH + r2 * H_PITCH + c) = v2;
                }
            }
        }
        __syncthreads();

        // ---- Layer 3 + masked accumulation (registers only) ----
        #pragma unroll
        for (int mt = 0; mt < 2; mt++)
            #pragma unroll
            for (int nt = 0; nt < 8; nt++)
                #pragma unroll
                for (int j = 0; j < 4; j++) acc[mt][nt][j] = 0.f;
        layer_mma<16, W_PITCH>(sH, sW3, mrow0, ncol0, lane, acc);
        {
            #pragma unroll
            for (int mt = 0; mt < 2; mt++) {
                const int r1 = mrow0 + mt * 16 + gr;
                const int r2 = r1 + 8;
                const float mk1 = sMsk[r1], mk2 = sMsk[r2];
                #pragma unroll
                for (int nt = 0; nt < 8; nt++) {
                    const int c = ncol0 + nt * 8 + tig * 2;
                    const float b0 = sm[OFF_B3 + c], b1v = sm[OFF_B3 + c + 1];
                    accum[nt * 2]     += mk1 * fmaxf(acc[mt][nt][0] + b0,  0.f)
                                       + mk2 * fmaxf(acc[mt][nt][2] + b0,  0.f);
                    accum[nt * 2 + 1] += mk1 * fmaxf(acc[mt][nt][1] + b1v, 0.f)
                                       + mk2 * fmaxf(acc[mt][nt][3] + b1v, 0.f);
                }
            }
        }
        // loop-top __syncthreads protects sH before next phase 1
    }
    if (cur_b >= 0) flush();
}

// ---------------------------------------------------------------------------
// Readout MLP per complex
// ---------------------------------------------------------------------------
__global__ void finalize_kernel(const float* __restrict__ Wr1,
                                const float* __restrict__ br1,
                                const float* __restrict__ Wr2,
                                const float* __restrict__ br2,
                                float* __restrict__ out) {
    const int b = blockIdx.x;
    const int c = threadIdx.x;   // 0..127
    __shared__ float repr[HH];
    __shared__ float red[HH];
    const int cnt = gCnt[b];
    const float denom = fmaxf((float)cnt, 1.0f);
    repr[c] = gAccum[b * HH + c] / denom;
    __syncthreads();
    float t = br1[c];
    #pragma unroll 4
    for (int k = 0; k < HH; k++) t += repr[k] * Wr1[k * HH + c];
    t = fmaxf(t, 0.f);
    red[c] = t * Wr2[c];
    __syncthreads();
    for (int s = 64; s > 0; s >>= 1) {
        if (c < s) red[c] += red[c + s];
        __syncthreads();
    }
    if (c == 0) out[b] = (cnt > 0) ? (red[0] + br2[0]) : 0.0f;
}

// ---------------------------------------------------------------------------
extern "C" void kernel_launch(void* const* d_in, const int* in_sizes, int n_in,
                              void* d_out, int out_size) {
    const float* ppos = (const float*)d_in[0];
    const float* lpos = (const float*)d_in[1];
    const float* pemb = (const float*)d_in[2];
    const float* lemb = (const float*)d_in[3];
    const float* W1   = (const float*)d_in[4];
    const float* b1   = (const float*)d_in[5];
    const float* W2   = (const float*)d_in[6];
    const float* b2   = (const float*)d_in[7];
    const float* W3   = (const float*)d_in[8];
    const float* b3   = (const float*)d_in[9];
    const float* Wr1  = (const float*)d_in[10];
    const float* br1  = (const float*)d_in[11];
    const float* Wr2  = (const float*)d_in[12];
    const float* br2  = (const float*)d_in[13];
    const int*   pt   = (const int*)d_in[14];
    const int*   lt   = (const int*)d_in[15];
    float* out = (float*)d_out;

    cudaFuncSetAttribute(main_kernel,
                         cudaFuncAttributeMaxDynamicSharedMemorySize, SMEM_BYTES);

    zero_kernel<<<1, 256>>>();
    main_kernel<<<GRIDX, 256, SMEM_BYTES>>>(ppos, lpos, pemb, lemb,
                                            W1, b1, W2, b2, W3, b3, pt, lt);
    finalize_kernel<<<BB, HH>>>(Wr1, br1, Wr2, br2, out);
}

// round 7
// speedup vs baseline: 3.7203x; 1.3816x over previous
#include <cuda_runtime.h>
#include <cuda_fp16.h>
#include <cstdint>
#include <math.h>

// Problem constants
#define BB 8
#define PP 512
#define LL 64
#define HH 128
#define NPT 20
#define NLT 16
#define NTILES (BB * 256)      // 2048 tiles of 128 pairs (2 p-atoms x 64 l-atoms)
#define GRIDX 148

// SMEM layout. Half regions first (indices in halves), float tail after.
#define W1R_PITCH_H 40         // 32 k-halves + pad (20 4B slots -> conflict-free)
#define W_PITCH_H   136        // 128 k-halves + pad (68 4B slots -> conflict-free)
#define H_PITCH_H   136
#define H_W1R 0                // 128*40  = 5120 halves
#define H_W2  5120             // 128*136 = 17408
#define H_W3  22528
#define H_H   39936            // activations [128][136]
#define HALves_TOTAL 57344     // ends at byte 114688
#define F_MSK 28672            // float index (byte 114688)
#define F_B2  28800
#define F_B3  28928
#define SMEM_FLOATS 29056
#define SMEM_BYTES (SMEM_FLOATS * 4)   // 116,224 bytes

// Global scratch (deterministic: rebuilt every launch)
__device__ float gPtab[NPT * HH];   // prot_emb@W1[0:128] + b1
__device__ float gLtab[NLT * HH];   // lig_emb@W1[128:256]
__device__ float gAccum[BB * HH];
__device__ int   gCnt[BB];

// ---------------------------------------------------------------------------
__device__ __forceinline__ void mma_f16(float c[4], const uint32_t a[4],
                                        uint32_t b0, uint32_t b1) {
    asm volatile(
        "mma.sync.aligned.m16n8k16.row.col.f32.f16.f16.f32 "
        "{%0,%1,%2,%3}, {%4,%5,%6,%7}, {%8,%9}, {%0,%1,%2,%3};"
        : "+f"(c[0]), "+f"(c[1]), "+f"(c[2]), "+f"(c[3])
        : "r"(a[0]), "r"(a[1]), "r"(a[2]), "r"(a[3]), "r"(b0), "r"(b1));
}

// Warp-level GEMM: acc[mt][nt][] += A(h)[mrow0..+32, :K] @ W[n][k]^T   (halves)
template<int KSTEPS, int WPITCH>
__device__ __forceinline__ void layer_mma(const __half* __restrict__ hA,
                                          const __half* __restrict__ Wb,
                                          int mrow0, int ncol0, int lane,
                                          float acc[2][8][4]) {
    const int gr = lane >> 2, tig = lane & 3;
    #pragma unroll
    for (int ks = 0; ks < KSTEPS; ks++) {
        uint32_t a[2][4];
        #pragma unroll
        for (int mt = 0; mt < 2; mt++) {
            const __half* base = hA + (mrow0 + mt * 16 + gr) * H_PITCH_H
                                    + ks * 16 + 2 * tig;
            a[mt][0] = *(const uint32_t*)(base);
            a[mt][1] = *(const uint32_t*)(base + 8 * H_PITCH_H);
            a[mt][2] = *(const uint32_t*)(base + 8);
            a[mt][3] = *(const uint32_t*)(base + 8 * H_PITCH_H + 8);
        }
        #pragma unroll
        for (int nt = 0; nt < 8; nt++) {
            const __half* bp = Wb + (ncol0 + nt * 8 + gr) * WPITCH
                                  + ks * 16 + 2 * tig;
            uint32_t b0 = *(const uint32_t*)(bp);
            uint32_t b1 = *(const uint32_t*)(bp + 8);
            mma_f16(acc[0][nt], a[0], b0, b1);
            mma_f16(acc[1][nt], a[1], b0, b1);
        }
    }
}

// ---------------------------------------------------------------------------
__global__ void zero_kernel() {
    int i = threadIdx.x;
    for (int j = i; j < BB * HH; j += 256) gAccum[j] = 0.f;
    if (i < BB) gCnt[i] = 0;
}

// ---------------------------------------------------------------------------
// Main kernel: fused pair MLP via mma.sync fp16 (fp32 accum), persistent CTAs
// ---------------------------------------------------------------------------
__global__ __launch_bounds__(256, 1)
void main_kernel(const float* __restrict__ ppos, const float* __restrict__ lpos,
                 const float* __restrict__ pemb, const float* __restrict__ lemb,
                 const float* __restrict__ W1, const float* __restrict__ b1,
                 const float* __restrict__ W2, const float* __restrict__ b2,
                 const float* __restrict__ W3, const float* __restrict__ b3,
                 const int* __restrict__ ptype, const int* __restrict__ ltype) {
    extern __shared__ float sm[];
    __half* smh = (__half*)sm;
    __half* sW1r = smh + H_W1R;
    __half* sW2  = smh + H_W2;
    __half* sW3  = smh + H_W3;
    __half* sH   = smh + H_H;
    float* sMsk = sm + F_MSK;

    const int tid = threadIdx.x;
    const int w = tid >> 5;
    const int lane = tid & 31;
    const int gr = lane >> 2, tig = lane & 3;

    // ---- Prologue: stage weights as fp16, n-major ----
    for (int idx = tid; idx < 32 * 128; idx += 256) {     // W1 radial rows
        int k = idx >> 7, n = idx & 127;
        sW1r[n * W1R_PITCH_H + k] = __float2half_rn(W1[(256 + k) * 128 + n]);
    }
    for (int idx = tid; idx < 128 * 128; idx += 256) {
        int k = idx >> 7, n = idx & 127;
        sW2[n * W_PITCH_H + k] = __float2half_rn(W2[k * 128 + n]);
        sW3[n * W_PITCH_H + k] = __float2half_rn(W3[k * 128 + n]);
    }
    if (tid < 128) { sm[F_B2 + tid] = b2[tid]; sm[F_B3 + tid] = b3[tid]; }

    // ---- Prologue: type tables (each CTA redundantly writes identical data) ----
    {
        const int c = tid & 127;
        if (tid < 128) {
            float tab[NPT];
            #pragma unroll
            for (int t = 0; t < NPT; t++) tab[t] = 0.f;
            for (int k = 0; k < 128; k++) {
                float wv = W1[k * 128 + c];
                #pragma unroll
                for (int t = 0; t < NPT; t++) tab[t] += wv * pemb[t * 128 + k];
            }
            float bb = b1[c];
            #pragma unroll
            for (int t = 0; t < NPT; t++) gPtab[t * 128 + c] = tab[t] + bb;
        } else {
            float tab[NLT];
            #pragma unroll
            for (int t = 0; t < NLT; t++) tab[t] = 0.f;
            for (int k = 0; k < 128; k++) {
                float wv = W1[(128 + k) * 128 + c];
                #pragma unroll
                for (int t = 0; t < NLT; t++) tab[t] += wv * lemb[t * 128 + k];
            }
            #pragma unroll
            for (int t = 0; t < NLT; t++) gLtab[t * 128 + c] = tab[t];
        }
    }
    __syncthreads();   // orders SMEM staging + own global table writes

    const int mrow0 = (w & 3) * 32;
    const int ncol0 = (w >> 2) * 64;

    float accum[16];
    #pragma unroll
    for (int j = 0; j < 16; j++) accum[j] = 0.f;
    int cur_b = -1, cnt_local = 0;

    const float invw  = 1.0f / (0.125f + 1e-8f);
    const float cstep = 8.0f / 31.0f;
    const int m_   = tid >> 1;      // pair handled in phase 1
    const int half = tid & 1;
    const int t_begin = (blockIdx.x * NTILES) / GRIDX;
    const int t_end   = ((blockIdx.x + 1) * NTILES) / GRIDX;

    auto flush = [&]() {
        #pragma unroll
        for (int j = 0; j < 16; j++) {
            #pragma unroll
            for (int off = 4; off < 32; off <<= 1)
                accum[j] += __shfl_xor_sync(0xffffffffu, accum[j], off);
        }
        if (lane < 4) {
            #pragma unroll
            for (int nt = 0; nt < 8; nt++) {
                atomicAdd(&gAccum[cur_b * HH + ncol0 + nt * 8 + lane * 2],     accum[nt * 2]);
                atomicAdd(&gAccum[cur_b * HH + ncol0 + nt * 8 + lane * 2 + 1], accum[nt * 2 + 1]);
            }
        }
        if (tid == 0) atomicAdd(&gCnt[cur_b], cnt_local);
        #pragma unroll
        for (int j = 0; j < 16; j++) accum[j] = 0.f;
    };

    for (int t = t_begin; t < t_end; t++) {
        const int b = t >> 8, ti = t & 255;
        if (b != cur_b) {
            if (cur_b >= 0) flush();
            cur_b = b; cnt_local = 0;
        }

        __syncthreads();   // protect sH/sMsk from previous tile's readers

        // ---- Phase 1: distances + fp16 radial basis into sH cols 0..31 ----
        {
            const int pl = ti * 2 + (m_ >> 6);
            const int ll = m_ & 63;
            const float* pp = ppos + (size_t)(b * PP + pl) * 3;
            const float* lp = lpos + (size_t)(b * LL + ll) * 3;
            const float dx = pp[0] - lp[0], dy = pp[1] - lp[1], dz = pp[2] - lp[2];
            const float dist = sqrtf(dx * dx + dy * dy + dz * dz);
            if (half == 0) sMsk[m_] = (dist < 8.0f) ? 1.0f : 0.0f;
            float rbv[16];
            #pragma unroll
            for (int j = 0; j < 16; j++) {
                const int bin = half * 16 + j;
                const float tt = (dist - (float)bin * cstep) * invw;
                rbv[j] = __expf(-0.5f * tt * tt);
            }
            #pragma unroll
            for (int j = 0; j < 8; j++) {
                *(__half2*)(sH + m_ * H_PITCH_H + half * 16 + 2 * j) =
                    __floats2half2_rn(rbv[2 * j], rbv[2 * j + 1]);
            }
            const int cnt = __syncthreads_count(half == 0 && dist < 8.0f);
            if (cnt == 0) continue;
            if (tid == 0) cnt_local += cnt;   // only tid 0 tracks; flush uses tid 0
        }

        float acc[2][8][4];

        // ---- Layer 1: rb @ W1r ----
        #pragma unroll
        for (int mt = 0; mt < 2; mt++)
            #pragma unroll
            for (int nt = 0; nt < 8; nt++)
                #pragma unroll
                for (int j = 0; j < 4; j++) acc[mt][nt][j] = 0.f;
        layer_mma<2, W1R_PITCH_H>(sH, sW1r, mrow0, ncol0, lane, acc);

        // ---- Epilogue 1: + Ptab[pt] + Ltab[lt], relu -> sH (fp16) ----
        __syncthreads();   // all warps done reading rb
        {
            const int pl = ti * 2 + ((w & 3) >> 1);
            const int pt = ptype[b * PP + pl];
            const float* PT = gPtab + pt * 128;
            #pragma unroll
            for (int mt = 0; mt < 2; mt++) {
                const int r1 = mrow0 + mt * 16 + gr;
                const int r2 = r1 + 8;
                const float* L1 = gLtab + ltype[b * LL + (r1 & 63)] * 128;
                const float* L2 = gLtab + ltype[b * LL + (r2 & 63)] * 128;
                #pragma unroll
                for (int nt = 0; nt < 8; nt++) {
                    const int c = ncol0 + nt * 8 + tig * 2;
                    const float p0 = PT[c], p1 = PT[c + 1];
                    *(__half2*)(sH + r1 * H_PITCH_H + c) = __floats2half2_rn(
                        fmaxf(acc[mt][nt][0] + p0 + L1[c],     0.f),
                        fmaxf(acc[mt][nt][1] + p1 + L1[c + 1], 0.f));
                    *(__half2*)(sH + r2 * H_PITCH_H + c) = __floats2half2_rn(
                        fmaxf(acc[mt][nt][2] + p0 + L2[c],     0.f),
                        fmaxf(acc[mt][nt][3] + p1 + L2[c + 1], 0.f));
                }
            }
        }
        __syncthreads();

        // ---- Layer 2 ----
        #pragma unroll
        for (int mt = 0; mt < 2; mt++)
            #pragma unroll
            for (int nt = 0; nt < 8; nt++)
                #pragma unroll
                for (int j = 0; j < 4; j++) acc[mt][nt][j] = 0.f;
        layer_mma<8, W_PITCH_H>(sH, sW2, mrow0, ncol0, lane, acc);
        __syncthreads();
        {
            #pragma unroll
            for (int mt = 0; mt < 2; mt++) {
                const int r1 = mrow0 + mt * 16 + gr;
                const int r2 = r1 + 8;
                #pragma unroll
                for (int nt = 0; nt < 8; nt++) {
                    const int c = ncol0 + nt * 8 + tig * 2;
                    const float b0 = sm[F_B2 + c], b1v = sm[F_B2 + c + 1];
                    *(__half2*)(sH + r1 * H_PITCH_H + c) = __floats2half2_rn(
                        fmaxf(acc[mt][nt][0] + b0,  0.f),
                        fmaxf(acc[mt][nt][1] + b1v, 0.f));
                    *(__half2*)(sH + r2 * H_PITCH_H + c) = __floats2half2_rn(
                        fmaxf(acc[mt][nt][2] + b0,  0.f),
                        fmaxf(acc[mt][nt][3] + b1v, 0.f));
                }
            }
        }
        __syncthreads();

        // ---- Layer 3 + masked accumulation (registers only) ----
        #pragma unroll
        for (int mt = 0; mt < 2; mt++)
            #pragma unroll
            for (int nt = 0; nt < 8; nt++)
                #pragma unroll
                for (int j = 0; j < 4; j++) acc[mt][nt][j] = 0.f;
        layer_mma<8, W_PITCH_H>(sH, sW3, mrow0, ncol0, lane, acc);
        {
            #pragma unroll
            for (int mt = 0; mt < 2; mt++) {
                const int r1 = mrow0 + mt * 16 + gr;
                const int r2 = r1 + 8;
                const float mk1 = sMsk[r1], mk2 = sMsk[r2];
                #pragma unroll
                for (int nt = 0; nt < 8; nt++) {
                    const int c = ncol0 + nt * 8 + tig * 2;
                    const float b0 = sm[F_B3 + c], b1v = sm[F_B3 + c + 1];
                    accum[nt * 2]     += mk1 * fmaxf(acc[mt][nt][0] + b0,  0.f)
                                       + mk2 * fmaxf(acc[mt][nt][2] + b0,  0.f);
                    accum[nt * 2 + 1] += mk1 * fmaxf(acc[mt][nt][1] + b1v, 0.f)
                                       + mk2 * fmaxf(acc[mt][nt][3] + b1v, 0.f);
                }
            }
        }
        // loop-top __syncthreads protects sH before next phase 1
    }
    if (cur_b >= 0) flush();
}

// ---------------------------------------------------------------------------
// Readout MLP per complex
// ---------------------------------------------------------------------------
__global__ void finalize_kernel(const float* __restrict__ Wr1,
                                const float* __restrict__ br1,
                                const float* __restrict__ Wr2,
                                const float* __restrict__ br2,
                                float* __restrict__ out) {
    const int b = blockIdx.x;
    const int c = threadIdx.x;   // 0..127
    __shared__ float repr[HH];
    __shared__ float red[HH];
    const int cnt = gCnt[b];
    const float denom = fmaxf((float)cnt, 1.0f);
    repr[c] = gAccum[b * HH + c] / denom;
    __syncthreads();
    float t = br1[c];
    #pragma unroll 4
    for (int k = 0; k < HH; k++) t += repr[k] * Wr1[k * HH + c];
    t = fmaxf(t, 0.f);
    red[c] = t * Wr2[c];
    __syncthreads();
    for (int s = 64; s > 0; s >>= 1) {
        if (c < s) red[c] += red[c + s];
        __syncthreads();
    }
    if (c == 0) out[b] = (cnt > 0) ? (red[0] + br2[0]) : 0.0f;
}

// ---------------------------------------------------------------------------
extern "C" void kernel_launch(void* const* d_in, const int* in_sizes, int n_in,
                              void* d_out, int out_size) {
    const float* ppos = (const float*)d_in[0];
    const float* lpos = (const float*)d_in[1];
    const float* pemb = (const float*)d_in[2];
    const float* lemb = (const float*)d_in[3];
    const float* W1   = (const float*)d_in[4];
    const float* b1   = (const float*)d_in[5];
    const float* W2   = (const float*)d_in[6];
    const float* b2   = (const float*)d_in[7];
    const float* W3   = (const float*)d_in[8];
    const float* b3   = (const float*)d_in[9];
    const float* Wr1  = (const float*)d_in[10];
    const float* br1  = (const float*)d_in[11];
    const float* Wr2  = (const float*)d_in[12];
    const float* br2  = (const float*)d_in[13];
    const int*   pt   = (const int*)d_in[14];
    const int*   lt   = (const int*)d_in[15];
    float* out = (float*)d_out;

    cudaFuncSetAttribute(main_kernel,
                         cudaFuncAttributeMaxDynamicSharedMemorySize, SMEM_BYTES);

    zero_kernel<<<1, 256>>>();
    main_kernel<<<GRIDX, 256, SMEM_BYTES>>>(ppos, lpos, pemb, lemb,
                                            W1, b1, W2, b2, W3, b3, pt, lt);
    finalize_kernel<<<BB, HH>>>(Wr1, br1, Wr2, br2, out);
}